// round 3
// baseline (speedup 1.0000x reference)
#include <cuda_runtime.h>
#include <cuda_bf16.h>

// Problem constants (fixed shapes from reference setup_inputs)
#define B_  2
#define K_  64
#define N_  16
#define HF_ 128
#define H_  128
#define W_  128
#define HWF (HF_*HF_)
#define NPIX ((double)(B_*K_*H_*W_))
#define LOG_EPS  (-27.631021115928547f)   /* logf(1e-12) */

// 2 blocks per (b,k): each covers 64 rows. 256 blocks total.
#define NBLK (B_*K_*2)

__device__ double g_partial[NBLK];

__global__ __launch_bounds__(256)
void gauss_main(const float* __restrict__ centers,
                const float* __restrict__ radius,
                const float* __restrict__ mask,
                const int* __restrict__ ind32,     // raw ind buffer, dtype sniffed
                const float* __restrict__ target,
                const float* __restrict__ peak)
{
    __shared__ float  s_pxy[2*N_];          // interleaved x,y per gaussian
    __shared__ float4 s_Ex[W_][N_/4];       // Ex[w][n]  (16 floats per w)
    __shared__ float4 s_Ey[64][N_/4];       // Ey[h_local][n]
    __shared__ float  s_negInv, s_m, s_logm;
    __shared__ float  s_warp[8];
    __shared__ int    s_idx;

    const int bid     = blockIdx.x;
    const int pair    = bid >> 1;           // (b,k) index == b*K + k
    const int rowbase = (bid & 1) * 64;     // which 64-row half
    const int b   = pair >> 6;
    const int k   = pair & 63;
    const int tid = threadIdx.x;

    // ---- dtype sniff for ind: int64 vs int32 ----
    // Reads stay within the first 256 bytes -> safe under either allocation.
    if (tid < 32) {
        int lo = ind32[2*tid];
        int hi = ind32[2*tid + 1];
        unsigned ok = __ballot_sync(0xffffffffu,
                                    hi == 0 && (unsigned)lo < (unsigned)HWF);
        if (tid == 0) {
            int e = pair;                   // element index b*K + k
            int idx = (ok == 0xffffffffu) ? ind32[2*e]   // int64 (low word)
                                          : ind32[e];    // int32
            // clamp defensively (never triggers on valid data)
            s_idx = min(max(idx, 0), HWF - 1);
        }
    }
    __syncthreads();
    const int idx = s_idx;

    // ---- Phase A: gather centers/radius/mask ----
    if (tid < 2*N_) {
        float v = centers[(b*2*N_ + tid)*HWF + idx];
        s_pxy[tid] = v + peak[pair*2 + (tid & 1)];
    }
    if (tid == 32) {
        float r  = radius[b*HWF + idx];
        s_negInv = -0.5f / (r*r);
        float m  = mask[b*K_ + k];
        s_m      = m;
        s_logm   = __logf(fmaxf(m, 1e-38f));
    }
    __syncthreads();

    // ---- Phase B: build separable exp tables ----
    // Ex: 128*16 = 2048 entries (e in [0,2048)); Ey: 64*16 = 1024 (e in [2048,3072))
    {
        const float negInv = s_negInv;
        #pragma unroll
        for (int i = 0; i < 12; i++) {
            int e = i*256 + tid;            // 0..3071
            int n = e & 15;
            int v = e >> 4;                 // 0..191
            if (v < 128) {
                float d = s_pxy[2*n] - (float)v;
                ((float*)s_Ex)[v*16 + n] = __expf(d*d*negInv);
            } else {
                int hl = v - 128;
                float d = s_pxy[2*n + 1] - (float)(hl + rowbase);
                ((float*)s_Ey)[hl*16 + n] = __expf(d*d*negInv);
            }
        }
    }
    __syncthreads();

    // ---- Phase C: per-pixel loss ----
    const int   w0   = tid & 127;
    const int   half = tid >> 7;
    const float m    = s_m;
    const float logm = s_logm;
    const float one_minus_m = 1.0f - m;

    // this thread's Ex column, kept in registers
    const float4 ex0 = s_Ex[w0][0];
    const float4 ex1 = s_Ex[w0][1];
    const float4 ex2 = s_Ex[w0][2];
    const float4 ex3 = s_Ex[w0][3];

    const float* __restrict__ tgt = target + (size_t)(pair*H_ + rowbase)*W_;

    float acc = 0.0f;
    #pragma unroll 4
    for (int it = 0; it < 32; it++) {
        int hl = 2*it + half;               // local row (broadcast LDS within warp)
        float4 ey0 = s_Ey[hl][0];
        float4 ey1 = s_Ey[hl][1];
        float4 ey2 = s_Ey[hl][2];
        float4 ey3 = s_Ey[hl][3];

        float g;
        g = ex0.x*ey0.x;
        g = fmaf(ex0.y, ey0.y, g);
        g = fmaf(ex0.z, ey0.z, g);
        g = fmaf(ex0.w, ey0.w, g);
        g = fmaf(ex1.x, ey1.x, g);
        g = fmaf(ex1.y, ey1.y, g);
        g = fmaf(ex1.z, ey1.z, g);
        g = fmaf(ex1.w, ey1.w, g);
        g = fmaf(ex2.x, ey2.x, g);
        g = fmaf(ex2.y, ey2.y, g);
        g = fmaf(ex2.z, ey2.z, g);
        g = fmaf(ex2.w, ey2.w, g);
        g = fmaf(ex3.x, ey3.x, g);
        g = fmaf(ex3.y, ey3.y, g);
        g = fmaf(ex3.z, ey3.z, g);
        g = fmaf(ex3.w, ey3.w, g);

        // p = m*sigmoid(g), t = m*target
        // log p     = log m - log(1+e),          e = exp(-g)
        // log (1-p) = log((1-m)+e) - log(1+e)
        float e  = __expf(-g);
        float L1 = __logf(1.0f + e);
        float lp  = fminf(fmaxf(logm - L1,                    LOG_EPS), 0.0f);
        float l1p = fminf(fmaxf(__logf(one_minus_m + e) - L1, LOG_EPS), 0.0f);

        float t = m * tgt[hl*W_ + w0];
        acc -= fmaf(t, lp - l1p, l1p);      // -(t*lp + (1-t)*l1p)
    }

    // ---- block reduction (deterministic tree) ----
    #pragma unroll
    for (int o = 16; o; o >>= 1)
        acc += __shfl_down_sync(0xffffffffu, acc, o);
    if ((tid & 31) == 0) s_warp[tid >> 5] = acc;
    __syncthreads();
    if (tid == 0) {
        double s = 0.0;
        #pragma unroll
        for (int i = 0; i < 8; i++) s += (double)s_warp[i];
        g_partial[bid] = s;
    }
}

__global__ __launch_bounds__(256)
void gauss_finish(float* __restrict__ out, int out_size)
{
    __shared__ double sh[NBLK];
    int tid = threadIdx.x;
    sh[tid] = g_partial[tid];
    __syncthreads();
    #pragma unroll
    for (int o = 128; o; o >>= 1) {
        if (tid < o) sh[tid] += sh[tid + o];
        __syncthreads();
    }
    float loss = (float)(sh[0] / NPIX);
    for (int i = tid; i < out_size; i += 256) out[i] = loss;
}

extern "C" void kernel_launch(void* const* d_in, const int* in_sizes, int n_in,
                              void* d_out, int out_size)
{
    const float* centers = (const float*)d_in[0];
    const float* radius  = (const float*)d_in[1];
    const float* mask    = (const float*)d_in[2];
    const int*   ind32   = (const int*)d_in[3];
    const float* target  = (const float*)d_in[4];
    const float* peak    = (const float*)d_in[5];

    gauss_main<<<NBLK, 256>>>(centers, radius, mask, ind32, target, peak);
    gauss_finish<<<1, 256>>>((float*)d_out, out_size);
}

// round 4
// speedup vs baseline: 1.0513x; 1.0513x over previous
#include <cuda_runtime.h>
#include <cuda_bf16.h>

// Problem constants (fixed shapes from reference setup_inputs)
#define B_  2
#define K_  64
#define N_  16
#define HF_ 128
#define H_  128
#define W_  128
#define HWF (HF_*HF_)
#define NPIX ((double)(B_*K_*H_*W_))
#define LOG_EPS  (-27.631021115928547f)   /* logf(1e-12) */

// 2 blocks per (b,k): each covers 64 rows. 256 blocks total.
#define NBLK (B_*K_*2)

__device__ double       g_partial[NBLK];
__device__ unsigned int g_ticket = 0u;

__device__ __forceinline__ unsigned long long f32x2_mul(unsigned long long a,
                                                        unsigned long long b)
{
    unsigned long long d;
    asm("mul.rn.f32x2 %0, %1, %2;" : "=l"(d) : "l"(a), "l"(b));
    return d;
}
__device__ __forceinline__ unsigned long long f32x2_fma(unsigned long long a,
                                                        unsigned long long b,
                                                        unsigned long long c)
{
    unsigned long long d;
    asm("fma.rn.f32x2 %0, %1, %2, %3;" : "=l"(d) : "l"(a), "l"(b), "l"(c));
    return d;
}
__device__ __forceinline__ float f32x2_hadd(unsigned long long v)
{
    unsigned int lo, hi;
    asm("mov.b64 {%0, %1}, %2;" : "=r"(lo), "=r"(hi) : "l"(v));
    return __uint_as_float(lo) + __uint_as_float(hi);
}

__global__ __launch_bounds__(256)
void gauss_fused(const float* __restrict__ centers,
                 const float* __restrict__ radius,
                 const float* __restrict__ mask,
                 const int* __restrict__ ind32,     // raw ind buffer, dtype sniffed
                 const float* __restrict__ target,
                 const float* __restrict__ peak,
                 float* __restrict__ out, int out_size)
{
    __shared__ float  s_pxy[2*N_];          // interleaved x,y per gaussian
    __shared__ float4 s_Ex[W_][N_/4];       // Ex[w][n]      (positive exps)
    __shared__ float4 s_Ey[64][N_/4];       // -Ey[hl][n]    (NEGATED exps)
    __shared__ float  s_negInv, s_m, s_logm;
    __shared__ float  s_warp[8];
    __shared__ int    s_idx;
    __shared__ int    s_last;

    const int bid     = blockIdx.x;
    const int pair    = bid >> 1;           // (b,k) index == b*K + k
    const int rowbase = (bid & 1) * 64;     // which 64-row half
    const int b   = pair >> 6;
    const int k   = pair & 63;
    const int tid = threadIdx.x;

    // ---- dtype sniff for ind: int64 vs int32 ----
    // Reads stay within the first 256 bytes -> safe under either allocation.
    if (tid < 32) {
        int lo = ind32[2*tid];
        int hi = ind32[2*tid + 1];
        unsigned ok = __ballot_sync(0xffffffffu,
                                    hi == 0 && (unsigned)lo < (unsigned)HWF);
        if (tid == 0) {
            int e = pair;
            int idx = (ok == 0xffffffffu) ? ind32[2*e]   // int64 (low word)
                                          : ind32[e];    // int32
            s_idx = min(max(idx, 0), HWF - 1);
        }
    }
    __syncthreads();
    const int idx = s_idx;

    // ---- Phase A: gather centers/radius/mask ----
    if (tid < 2*N_) {
        float v = centers[(b*2*N_ + tid)*HWF + idx];
        s_pxy[tid] = v + peak[pair*2 + (tid & 1)];
    }
    if (tid == 32) {
        float r  = radius[b*HWF + idx];
        s_negInv = -0.5f / (r*r);
        float m  = mask[b*K_ + k];
        s_m      = m;
        s_logm   = __logf(fmaxf(m, 1e-38f));
    }
    __syncthreads();

    // ---- Phase B: separable exp tables (Ey stored NEGATED) ----
    {
        const float negInv = s_negInv;
        #pragma unroll
        for (int i = 0; i < 12; i++) {
            int e = i*256 + tid;            // 0..3071
            int n = e & 15;
            int v = e >> 4;                 // 0..191
            if (v < 128) {
                float d = s_pxy[2*n] - (float)v;
                ((float*)s_Ex)[v*16 + n] = __expf(d*d*negInv);
            } else {
                int hl = v - 128;
                float d = s_pxy[2*n + 1] - (float)(hl + rowbase);
                ((float*)s_Ey)[hl*16 + n] = -__expf(d*d*negInv);
            }
        }
    }
    __syncthreads();

    // ---- Phase C: per-pixel loss (packed f32x2 dot: yields -g directly) ----
    const int   w0   = tid & 127;
    const int   half = tid >> 7;
    const float m    = s_m;
    const float logm = s_logm;
    const float one_minus_m = 1.0f - m;

    // this thread's Ex column as 8 packed f32x2 values, kept in registers
    unsigned long long ex[8];
    {
        const ulonglong2* exp_ = (const ulonglong2*)&s_Ex[w0][0];
        #pragma unroll
        for (int j = 0; j < 4; j++) {
            ulonglong2 v = exp_[j];
            ex[2*j]   = v.x;
            ex[2*j+1] = v.y;
        }
    }

    const float* __restrict__ tgt = target + (size_t)(pair*H_ + rowbase)*W_;

    float acc = 0.0f;
    #pragma unroll 4
    for (int it = 0; it < 32; it++) {
        int hl = 2*it + half;               // local row (broadcast LDS within warp)
        const ulonglong2* eyp = (const ulonglong2*)&s_Ey[hl][0];
        ulonglong2 e0 = eyp[0];
        ulonglong2 e1 = eyp[1];
        ulonglong2 e2 = eyp[2];
        ulonglong2 e3 = eyp[3];

        unsigned long long a2 = f32x2_mul(ex[0], e0.x);
        a2 = f32x2_fma(ex[1], e0.y, a2);
        a2 = f32x2_fma(ex[2], e1.x, a2);
        a2 = f32x2_fma(ex[3], e1.y, a2);
        a2 = f32x2_fma(ex[4], e2.x, a2);
        a2 = f32x2_fma(ex[5], e2.y, a2);
        a2 = f32x2_fma(ex[6], e3.x, a2);
        a2 = f32x2_fma(ex[7], e3.y, a2);
        float ng = f32x2_hadd(a2);          // = -g  (Ey negated)

        // p = m*sigmoid(g), t = m*target;  e = exp(-g)
        // log p     = log m - log(1+e)
        // log (1-p) = log((1-m)+e) - log(1+e)
        float e  = __expf(ng);
        float L1 = __logf(1.0f + e);
        float lp  = fmaxf(logm - L1,                    LOG_EPS);
        float l1p = fmaxf(__logf(one_minus_m + e) - L1, LOG_EPS);

        float t = m * tgt[hl*W_ + w0];
        acc -= fmaf(t, lp - l1p, l1p);      // -(t*lp + (1-t)*l1p)
    }

    // ---- block reduction (deterministic tree) ----
    #pragma unroll
    for (int o = 16; o; o >>= 1)
        acc += __shfl_down_sync(0xffffffffu, acc, o);
    if ((tid & 31) == 0) s_warp[tid >> 5] = acc;
    __syncthreads();
    if (tid == 0) {
        double s = 0.0;
        #pragma unroll
        for (int i = 0; i < 8; i++) s += (double)s_warp[i];
        g_partial[bid] = s;
        __threadfence();
        unsigned int v = atomicAdd(&g_ticket, 1u);
        s_last = (v == NBLK - 1u) ? 1 : 0;
    }
    __syncthreads();

    // ---- last block: deterministic final tree + output ----
    if (s_last) {
        __shared__ double sh[NBLK];
        sh[tid] = g_partial[tid];
        __syncthreads();
        #pragma unroll
        for (int o = 128; o; o >>= 1) {
            if (tid < o) sh[tid] += sh[tid + o];
            __syncthreads();
        }
        float loss = (float)(sh[0] / NPIX);
        for (int i = tid; i < out_size; i += 256) out[i] = loss;
        if (tid == 0) g_ticket = 0u;        // reset for next graph replay
    }
}

extern "C" void kernel_launch(void* const* d_in, const int* in_sizes, int n_in,
                              void* d_out, int out_size)
{
    const float* centers = (const float*)d_in[0];
    const float* radius  = (const float*)d_in[1];
    const float* mask    = (const float*)d_in[2];
    const int*   ind32   = (const int*)d_in[3];
    const float* target  = (const float*)d_in[4];
    const float* peak    = (const float*)d_in[5];

    gauss_fused<<<NBLK, 256>>>(centers, radius, mask, ind32, target, peak,
                               (float*)d_out, out_size);
}